// round 1
// baseline (speedup 1.0000x reference)
#include <cuda_runtime.h>

#define NN 50000
#define EE 400000
#define BBATCH 8
#define NDIM 32
#define EDIM 16
#define HH 128
#define LL 3

#define BM 128
#define BK 16

// ---------------- device scratch (static: no runtime allocation allowed) ----
__device__ float g_h[(size_t)NN * HH];        // node features      (25.6 MB)
__device__ float g_e[(size_t)EE * HH];        // edge embeddings    (204.8 MB)
__device__ float g_aggr[(size_t)NN * HH];     // per-layer aggregation
__device__ int   g_src[EE];
__device__ int   g_dst[EE];
__device__ int   g_batchv[NN];
__device__ float g_pooled[BBATCH * HH];
__device__ float g_counts[BBATCH];
__device__ int   g_is64;

// ---------------- index dtype detection + conversion ----------------------
__global__ void detect_kernel(const unsigned int* __restrict__ ei) {
    // If data is little-endian int64 with values in [0, 50000), every odd
    // 32-bit word is zero. 256 samples make false positives ~impossible.
    int ok = 1;
    for (int i = 0; i < 256; i++) {
        if (ei[2 * i + 1] != 0u) { ok = 0; break; }
    }
    g_is64 = ok;
}

__global__ void convert_kernel(const void* __restrict__ ei, const void* __restrict__ bt) {
    const int is64 = g_is64;
    int i = blockIdx.x * blockDim.x + threadIdx.x;
    int stride = gridDim.x * blockDim.x;
    for (int k = i; k < EE; k += stride) {
        if (is64) {
            g_src[k] = (int)((const long long*)ei)[k];
            g_dst[k] = (int)((const long long*)ei)[EE + k];
        } else {
            g_src[k] = ((const int*)ei)[k];
            g_dst[k] = ((const int*)ei)[EE + k];
        }
    }
    for (int k = i; k < NN; k += stride) {
        g_batchv[k] = is64 ? (int)((const long long*)bt)[k] : ((const int*)bt)[k];
    }
}

// ---------------- embeddings ----------------------------------------------
__global__ void node_embed_kernel(const float* __restrict__ x,
                                  const float* __restrict__ Wn,
                                  const float* __restrict__ bn) {
    __shared__ float sW[NDIM * HH];
    __shared__ float sb[HH];
    for (int i = threadIdx.x; i < NDIM * HH; i += blockDim.x) sW[i] = Wn[i];
    if (threadIdx.x < HH) sb[threadIdx.x] = bn[threadIdx.x];
    __syncthreads();
    int g = blockIdx.x * blockDim.x + threadIdx.x;
    int stride = gridDim.x * blockDim.x;
    const int total = NN * 32;  // 4 output cols per thread
    for (; g < total; g += stride) {
        int n = g >> 5;
        int c = (g & 31) * 4;
        const float* xr = x + (size_t)n * NDIM;
        float4 o = make_float4(sb[c], sb[c + 1], sb[c + 2], sb[c + 3]);
#pragma unroll
        for (int k = 0; k < NDIM; k++) {
            float a = __ldg(xr + k);
            float4 w = *(const float4*)&sW[k * HH + c];
            o.x = fmaf(a, w.x, o.x); o.y = fmaf(a, w.y, o.y);
            o.z = fmaf(a, w.z, o.z); o.w = fmaf(a, w.w, o.w);
        }
        *(float4*)&g_h[(size_t)n * HH + c] = o;
    }
}

__global__ void edge_embed_kernel(const float* __restrict__ ea,
                                  const float* __restrict__ We,
                                  const float* __restrict__ be) {
    __shared__ float sW[EDIM * HH];
    __shared__ float sb[HH];
    for (int i = threadIdx.x; i < EDIM * HH; i += blockDim.x) sW[i] = We[i];
    if (threadIdx.x < HH) sb[threadIdx.x] = be[threadIdx.x];
    __syncthreads();
    int g = blockIdx.x * blockDim.x + threadIdx.x;
    int stride = gridDim.x * blockDim.x;
    const int total = EE * 32;
    for (; g < total; g += stride) {
        int i = g >> 5;
        int c = (g & 31) * 4;
        const float* row = ea + (size_t)i * EDIM;
        float4 o = make_float4(sb[c], sb[c + 1], sb[c + 2], sb[c + 3]);
#pragma unroll
        for (int k = 0; k < EDIM; k++) {
            float a = __ldg(row + k);
            float4 w = *(const float4*)&sW[k * HH + c];
            o.x = fmaf(a, w.x, o.x); o.y = fmaf(a, w.y, o.y);
            o.z = fmaf(a, w.z, o.z); o.w = fmaf(a, w.w, o.w);
        }
        *(float4*)&g_e[(size_t)i * HH + c] = o;
    }
}

// ---------------- zeroing --------------------------------------------------
__global__ void zero_aggr_kernel() {
    int i = blockIdx.x * blockDim.x + threadIdx.x;
    int stride = gridDim.x * blockDim.x;
    float4 z = make_float4(0.f, 0.f, 0.f, 0.f);
    const int n4 = NN * HH / 4;
    for (int k = i; k < n4; k += stride) ((float4*)g_aggr)[k] = z;
}

__global__ void zero_pool_kernel() {
    for (int k = threadIdx.x; k < BBATCH * HH; k += blockDim.x) g_pooled[k] = 0.f;
    if (threadIdx.x < BBATCH) g_counts[threadIdx.x] = 0.f;
}

// ---------------- fused edge MLP + scatter ---------------------------------
// Per block: 128 edges x 128 outputs. Phase1: K=384 (gathered), Phase2: K=128.
// Dynamic smem: sA[BK][BM], sB[BK][HH], sH[HH][BM], sDst[BM], sSrc[BM]
__global__ __launch_bounds__(256, 2)
void edge_mlp_kernel(const float* __restrict__ W1, const float* __restrict__ b1v,
                     const float* __restrict__ W2, const float* __restrict__ b2v) {
    extern __shared__ float smem[];
    float* sA = smem;                       // BK*BM
    float* sB = sA + BK * BM;               // BK*HH
    float* sH = sB + BK * HH;               // HH*BM (hidden, transposed [k][m])
    int* sDst = (int*)(sH + HH * BM);
    int* sSrc = sDst + BM;

    const int tid = threadIdx.x;
    const int ebase = blockIdx.x * BM;
    const int tx = tid & 15;
    const int ty = tid >> 4;

    if (tid < BM) sDst[tid] = g_dst[ebase + tid];
    else          sSrc[tid - BM] = g_src[ebase + tid - BM];
    __syncthreads();

    const int r_g = tid >> 1;          // gather row (0..127)
    const int kq  = (tid & 1) * 8;     // k offset within tile (0 or 8)
    const float* base0 = g_h + (size_t)sDst[r_g] * HH;   // h[dst]
    const float* base1 = g_h + (size_t)sSrc[r_g] * HH;   // h[src]
    const float* base2 = g_e + (size_t)(ebase + r_g) * HH;  // e[edge]

    float acc[8][8];
#pragma unroll
    for (int i = 0; i < 8; i++)
#pragma unroll
        for (int j = 0; j < 8; j++) acc[i][j] = 0.f;

    // W-tile staging coords (2 float4 per thread per tile)
    const int wkr = (tid * 2) >> 5;          // row in tile (0..15)
    const int wc4 = ((tid * 2) & 31) * 4;    // col (0,8,...,120)

    // -------- phase 1: hidden = relu(gathered_in @ W1 + b1) --------
#pragma unroll 1
    for (int reg = 0; reg < 3; reg++) {
        const float* bp = (reg == 0) ? base0 : (reg == 1) ? base1 : base2;
        const float* wb = W1 + (size_t)reg * HH * HH;
#pragma unroll 1
        for (int kt = 0; kt < HH; kt += BK) {
            float4 v0 = *(const float4*)(bp + kt + kq);
            float4 v1 = *(const float4*)(bp + kt + kq + 4);
            sA[(kq + 0) * BM + r_g] = v0.x;
            sA[(kq + 1) * BM + r_g] = v0.y;
            sA[(kq + 2) * BM + r_g] = v0.z;
            sA[(kq + 3) * BM + r_g] = v0.w;
            sA[(kq + 4) * BM + r_g] = v1.x;
            sA[(kq + 5) * BM + r_g] = v1.y;
            sA[(kq + 6) * BM + r_g] = v1.z;
            sA[(kq + 7) * BM + r_g] = v1.w;
            const float* wp = wb + (size_t)(kt + wkr) * HH + wc4;
            *(float4*)&sB[wkr * HH + wc4]     = *(const float4*)wp;
            *(float4*)&sB[wkr * HH + wc4 + 4] = *(const float4*)(wp + 4);
            __syncthreads();
#pragma unroll
            for (int k = 0; k < BK; k++) {
                float4 a0 = *(float4*)&sA[k * BM + ty * 4];
                float4 a1 = *(float4*)&sA[k * BM + 64 + ty * 4];
                float4 bb0 = *(float4*)&sB[k * HH + tx * 4];
                float4 bb1 = *(float4*)&sB[k * HH + 64 + tx * 4];
                float a[8] = {a0.x, a0.y, a0.z, a0.w, a1.x, a1.y, a1.z, a1.w};
                float b[8] = {bb0.x, bb0.y, bb0.z, bb0.w, bb1.x, bb1.y, bb1.z, bb1.w};
#pragma unroll
                for (int i = 0; i < 8; i++)
#pragma unroll
                    for (int j = 0; j < 8; j++)
                        acc[i][j] = fmaf(a[i], b[j], acc[i][j]);
            }
            __syncthreads();
        }
    }

    // bias + relu -> sH (transposed [hidden_ch][edge_row])
#pragma unroll
    for (int j = 0; j < 8; j++) {
        int c = (j < 4) ? (tx * 4 + j) : (64 + tx * 4 + (j - 4));
        float bb = b1v[c];
#pragma unroll
        for (int i = 0; i < 8; i++) {
            int r = (i < 4) ? (ty * 4 + i) : (64 + ty * 4 + (i - 4));
            float v = acc[i][j] + bb;
            sH[c * BM + r] = (v > 0.f) ? v : 0.f;
            acc[i][j] = 0.f;
        }
    }
    __syncthreads();

    // -------- phase 2: out = hidden @ W2 + b2 --------
#pragma unroll 1
    for (int kt = 0; kt < HH; kt += BK) {
        const float* wp = W2 + (size_t)(kt + wkr) * HH + wc4;
        *(float4*)&sB[wkr * HH + wc4]     = *(const float4*)wp;
        *(float4*)&sB[wkr * HH + wc4 + 4] = *(const float4*)(wp + 4);
        __syncthreads();
#pragma unroll
        for (int k = 0; k < BK; k++) {
            float4 a0 = *(float4*)&sH[(kt + k) * BM + ty * 4];
            float4 a1 = *(float4*)&sH[(kt + k) * BM + 64 + ty * 4];
            float4 bb0 = *(float4*)&sB[k * HH + tx * 4];
            float4 bb1 = *(float4*)&sB[k * HH + 64 + tx * 4];
            float a[8] = {a0.x, a0.y, a0.z, a0.w, a1.x, a1.y, a1.z, a1.w};
            float b[8] = {bb0.x, bb0.y, bb0.z, bb0.w, bb1.x, bb1.y, bb1.z, bb1.w};
#pragma unroll
            for (int i = 0; i < 8; i++)
#pragma unroll
                for (int j = 0; j < 8; j++)
                    acc[i][j] = fmaf(a[i], b[j], acc[i][j]);
        }
        __syncthreads();
    }

    // -------- scatter: aggr[dst] += out --------
    float bias2[8];
#pragma unroll
    for (int j = 0; j < 8; j++) {
        int c = (j < 4) ? (tx * 4 + j) : (64 + tx * 4 + (j - 4));
        bias2[j] = b2v[c];
    }
#pragma unroll
    for (int i = 0; i < 8; i++) {
        int r = (i < 4) ? (ty * 4 + i) : (64 + ty * 4 + (i - 4));
        float* op = g_aggr + (size_t)sDst[r] * HH;
#pragma unroll
        for (int j = 0; j < 8; j++) {
            int c = (j < 4) ? (tx * 4 + j) : (64 + tx * 4 + (j - 4));
            atomicAdd(op + c, acc[i][j] + bias2[j]);
        }
    }
}

// ---------------- fused node update (K=256, in-place residual) --------------
__global__ __launch_bounds__(256, 2)
void node_mlp_kernel(const float* __restrict__ W1, const float* __restrict__ b1v,
                     const float* __restrict__ W2, const float* __restrict__ b2v) {
    extern __shared__ float smem[];
    float* sA = smem;
    float* sB = sA + BK * BM;
    float* sH = sB + BK * HH;

    const int tid = threadIdx.x;
    const int nbase = blockIdx.x * BM;
    const int tx = tid & 15;
    const int ty = tid >> 4;

    const int r_g = tid >> 1;
    const int kq  = (tid & 1) * 8;
    int gnode = nbase + r_g;
    if (gnode >= NN) gnode = NN - 1;   // clamp (stores guarded below)
    const float* base0 = g_h + (size_t)gnode * HH;
    const float* base1 = g_aggr + (size_t)gnode * HH;

    float acc[8][8];
#pragma unroll
    for (int i = 0; i < 8; i++)
#pragma unroll
        for (int j = 0; j < 8; j++) acc[i][j] = 0.f;

    const int wkr = (tid * 2) >> 5;
    const int wc4 = ((tid * 2) & 31) * 4;

#pragma unroll 1
    for (int reg = 0; reg < 2; reg++) {
        const float* bp = (reg == 0) ? base0 : base1;
        const float* wb = W1 + (size_t)reg * HH * HH;
#pragma unroll 1
        for (int kt = 0; kt < HH; kt += BK) {
            float4 v0 = *(const float4*)(bp + kt + kq);
            float4 v1 = *(const float4*)(bp + kt + kq + 4);
            sA[(kq + 0) * BM + r_g] = v0.x;
            sA[(kq + 1) * BM + r_g] = v0.y;
            sA[(kq + 2) * BM + r_g] = v0.z;
            sA[(kq + 3) * BM + r_g] = v0.w;
            sA[(kq + 4) * BM + r_g] = v1.x;
            sA[(kq + 5) * BM + r_g] = v1.y;
            sA[(kq + 6) * BM + r_g] = v1.z;
            sA[(kq + 7) * BM + r_g] = v1.w;
            const float* wp = wb + (size_t)(kt + wkr) * HH + wc4;
            *(float4*)&sB[wkr * HH + wc4]     = *(const float4*)wp;
            *(float4*)&sB[wkr * HH + wc4 + 4] = *(const float4*)(wp + 4);
            __syncthreads();
#pragma unroll
            for (int k = 0; k < BK; k++) {
                float4 a0 = *(float4*)&sA[k * BM + ty * 4];
                float4 a1 = *(float4*)&sA[k * BM + 64 + ty * 4];
                float4 bb0 = *(float4*)&sB[k * HH + tx * 4];
                float4 bb1 = *(float4*)&sB[k * HH + 64 + tx * 4];
                float a[8] = {a0.x, a0.y, a0.z, a0.w, a1.x, a1.y, a1.z, a1.w};
                float b[8] = {bb0.x, bb0.y, bb0.z, bb0.w, bb1.x, bb1.y, bb1.z, bb1.w};
#pragma unroll
                for (int i = 0; i < 8; i++)
#pragma unroll
                    for (int j = 0; j < 8; j++)
                        acc[i][j] = fmaf(a[i], b[j], acc[i][j]);
            }
            __syncthreads();
        }
    }

#pragma unroll
    for (int j = 0; j < 8; j++) {
        int c = (j < 4) ? (tx * 4 + j) : (64 + tx * 4 + (j - 4));
        float bb = b1v[c];
#pragma unroll
        for (int i = 0; i < 8; i++) {
            int r = (i < 4) ? (ty * 4 + i) : (64 + ty * 4 + (i - 4));
            float v = acc[i][j] + bb;
            sH[c * BM + r] = (v > 0.f) ? v : 0.f;
            acc[i][j] = 0.f;
        }
    }
    __syncthreads();

#pragma unroll 1
    for (int kt = 0; kt < HH; kt += BK) {
        const float* wp = W2 + (size_t)(kt + wkr) * HH + wc4;
        *(float4*)&sB[wkr * HH + wc4]     = *(const float4*)wp;
        *(float4*)&sB[wkr * HH + wc4 + 4] = *(const float4*)(wp + 4);
        __syncthreads();
#pragma unroll
        for (int k = 0; k < BK; k++) {
            float4 a0 = *(float4*)&sH[(kt + k) * BM + ty * 4];
            float4 a1 = *(float4*)&sH[(kt + k) * BM + 64 + ty * 4];
            float4 bb0 = *(float4*)&sB[k * HH + tx * 4];
            float4 bb1 = *(float4*)&sB[k * HH + 64 + tx * 4];
            float a[8] = {a0.x, a0.y, a0.z, a0.w, a1.x, a1.y, a1.z, a1.w};
            float b[8] = {bb0.x, bb0.y, bb0.z, bb0.w, bb1.x, bb1.y, bb1.z, bb1.w};
#pragma unroll
            for (int i = 0; i < 8; i++)
#pragma unroll
                for (int j = 0; j < 8; j++)
                    acc[i][j] = fmaf(a[i], b[j], acc[i][j]);
        }
        __syncthreads();
    }

    // residual in place: h += upd + b2 (rows are block-exclusive -> no atomics)
    float bias2[8];
#pragma unroll
    for (int j = 0; j < 8; j++) {
        int c = (j < 4) ? (tx * 4 + j) : (64 + tx * 4 + (j - 4));
        bias2[j] = b2v[c];
    }
#pragma unroll
    for (int i = 0; i < 8; i++) {
        int r = (i < 4) ? (ty * 4 + i) : (64 + ty * 4 + (i - 4));
        int node = nbase + r;
        if (node < NN) {
            float* op = g_h + (size_t)node * HH;
#pragma unroll
            for (int j = 0; j < 8; j++) {
                int c = (j < 4) ? (tx * 4 + j) : (64 + tx * 4 + (j - 4));
                op[c] += acc[i][j] + bias2[j];
            }
        }
    }
}

// ---------------- pooling ---------------------------------------------------
__global__ void pool_kernel() {
    __shared__ float sp[BBATCH * HH];
    __shared__ float sc[BBATCH];
    for (int i = threadIdx.x; i < BBATCH * HH; i += blockDim.x) sp[i] = 0.f;
    if (threadIdx.x < BBATCH) sc[threadIdx.x] = 0.f;
    __syncthreads();
    int g = blockIdx.x * blockDim.x + threadIdx.x;
    int stride = gridDim.x * blockDim.x;
    const int total = NN * HH;
    for (int idx = g; idx < total; idx += stride) {
        int n = idx >> 7;
        int j = idx & 127;
        int b = g_batchv[n];
        atomicAdd(&sp[b * HH + j], g_h[idx]);
        if (j == 0) atomicAdd(&sc[b], 1.f);
    }
    __syncthreads();
    for (int i = threadIdx.x; i < BBATCH * HH; i += blockDim.x)
        atomicAdd(&g_pooled[i], sp[i]);
    if (threadIdx.x < BBATCH) atomicAdd(&g_counts[threadIdx.x], sc[threadIdx.x]);
}

// ---------------- readout MLP (single block, includes global-feature embed) -
__global__ void readout_kernel(const float* __restrict__ gf,
                               const float* __restrict__ Wg, const float* __restrict__ bg,
                               const float* __restrict__ rW1, const float* __restrict__ rb1,
                               const float* __restrict__ rW2, const float* __restrict__ rb2,
                               const float* __restrict__ rW3, const float* __restrict__ rb3,
                               float* __restrict__ out) {
    __shared__ float fin[BBATCH * 2 * HH];
    __shared__ float h1[BBATCH * HH];
    __shared__ float h2[BBATCH * 64];
    const int t = threadIdx.x;
    for (int idx = t; idx < BBATCH * 2 * HH; idx += blockDim.x) {
        int b = idx >> 8;
        int c = idx & 255;
        float v;
        if (c < HH) {
            float cnt = g_counts[b];
            if (cnt < 1.f) cnt = 1.f;
            v = g_pooled[b * HH + c] / cnt;
        } else {
            v = gf[b] * Wg[c - HH] + bg[c - HH];
        }
        fin[idx] = v;
    }
    __syncthreads();
    for (int idx = t; idx < BBATCH * HH; idx += blockDim.x) {
        int b = idx >> 7;
        int j = idx & 127;
        float s = rb1[j];
        for (int k = 0; k < 2 * HH; k++)
            s = fmaf(fin[b * 256 + k], rW1[k * HH + j], s);
        h1[idx] = (s > 0.f) ? s : 0.f;
    }
    __syncthreads();
    for (int idx = t; idx < BBATCH * 64; idx += blockDim.x) {
        int b = idx >> 6;
        int j = idx & 63;
        float s = rb2[j];
        for (int k = 0; k < HH; k++)
            s = fmaf(h1[b * HH + k], rW2[k * 64 + j], s);
        h2[idx] = (s > 0.f) ? s : 0.f;
    }
    __syncthreads();
    if (t < BBATCH) {
        float s = rb3[0];
        for (int k = 0; k < 64; k++)
            s = fmaf(h2[t * 64 + k], rW3[k], s);
        out[t] = s;
    }
}

// ---------------- host launcher --------------------------------------------
extern "C" void kernel_launch(void* const* d_in, const int* in_sizes, int n_in,
                              void* d_out, int out_size) {
    // Map inputs by element count (robust to metadata ordering; ties broken by
    // relative order, identical in both setup_inputs and reference signature).
    const float *x = 0, *ea = 0, *gf = 0;
    const void  *ei = 0, *bt = 0;
    const float *Wn = 0, *bn = 0, *We = 0, *be = 0, *Wg = 0, *bg = 0;
    const float *mW1 = 0, *mb1 = 0, *mW2 = 0, *mb2 = 0;
    const float *uW1 = 0, *ub1 = 0, *uW2 = 0, *ub2 = 0;
    const float *rW1 = 0, *rb1 = 0, *rW2 = 0, *rb2 = 0, *rW3 = 0, *rb3 = 0;
    int c128 = 0, c384 = 0, c49 = 0, c64 = 0;
    for (int i = 0; i < n_in; i++) {
        const void* p = d_in[i];
        switch (in_sizes[i]) {
            case 1600000: x = (const float*)p; break;
            case 6400000: ea = (const float*)p; break;
            case 8:       gf = (const float*)p; break;
            case 800000:  ei = p; break;
            case 50000:   bt = p; break;
            case 4096:    Wn = (const float*)p; break;
            case 2048:    We = (const float*)p; break;
            case 147456:  mW1 = (const float*)p; break;
            case 98304:   uW1 = (const float*)p; break;
            case 32768:   rW1 = (const float*)p; break;
            case 8192:    rW2 = (const float*)p; break;
            case 1:       rb3 = (const float*)p; break;
            case 128:
                if (c128 == 0) bn = (const float*)p;
                else if (c128 == 1) be = (const float*)p;
                else if (c128 == 2) Wg = (const float*)p;
                else if (c128 == 3) bg = (const float*)p;
                else rb1 = (const float*)p;
                c128++;
                break;
            case 384:
                if (c384 == 0) mb1 = (const float*)p;
                else if (c384 == 1) mb2 = (const float*)p;
                else if (c384 == 2) ub1 = (const float*)p;
                else ub2 = (const float*)p;
                c384++;
                break;
            case 49152:
                if (c49 == 0) mW2 = (const float*)p;
                else uW2 = (const float*)p;
                c49++;
                break;
            case 64:
                if (c64 == 0) rb2 = (const float*)p;
                else rW3 = (const float*)p;
                c64++;
                break;
            default: break;
        }
    }
    float* out = (float*)d_out;
    (void)out_size;

    const int SMEM_MLP = (BK * BM + BK * HH + HH * BM) * 4 + 2 * BM * 4;
    cudaFuncSetAttribute(edge_mlp_kernel, cudaFuncAttributeMaxDynamicSharedMemorySize, SMEM_MLP);
    cudaFuncSetAttribute(node_mlp_kernel, cudaFuncAttributeMaxDynamicSharedMemorySize, SMEM_MLP);

    detect_kernel<<<1, 1>>>((const unsigned int*)ei);
    convert_kernel<<<1024, 256>>>(ei, bt);
    node_embed_kernel<<<3200, 256>>>(x, Wn, bn);
    edge_embed_kernel<<<6400, 256>>>(ea, We, be);

    for (int l = 0; l < LL; l++) {
        zero_aggr_kernel<<<1600, 256>>>();
        edge_mlp_kernel<<<EE / BM, 256, SMEM_MLP>>>(
            mW1 + (size_t)l * 3 * HH * HH, mb1 + l * HH,
            mW2 + (size_t)l * HH * HH, mb2 + l * HH);
        node_mlp_kernel<<<(NN + BM - 1) / BM, 256, SMEM_MLP>>>(
            uW1 + (size_t)l * 2 * HH * HH, ub1 + l * HH,
            uW2 + (size_t)l * HH * HH, ub2 + l * HH);
    }

    zero_pool_kernel<<<1, 256>>>();
    pool_kernel<<<1024, 256>>>();
    readout_kernel<<<1, 256>>>(gf, Wg, bg, rW1, rb1, rW2, rb2, rW3, rb3, out);
}

// round 2
// speedup vs baseline: 1.9053x; 1.9053x over previous
#include <cuda_runtime.h>

#define NN 50000
#define EE 400000
#define BBATCH 8
#define NDIM 32
#define EDIM 16
#define HH 128
#define LL 3

#define BM 128
#define BK 16

// ---------------- device scratch ----------------
__device__ float g_h[(size_t)NN * HH];        // node features (25.6 MB)
__device__ float g_pa[(size_t)NN * HH];       // h @ W1a  (dst part)
__device__ float g_pb[(size_t)NN * HH];       // h @ W1b  (src part)
__device__ float g_aggr[(size_t)NN * HH];     // per-layer aggregation
__device__ float g_wec[LL * EDIM * HH];       // fused We@W1c per layer
__device__ float g_b1e[LL * HH];              // fused bias1 per layer
__device__ int   g_src[EE];
__device__ int   g_dst[EE];
__device__ int   g_batchv[NN];
__device__ float g_pooled[BBATCH * HH];
__device__ float g_counts[BBATCH];
__device__ int   g_is64;

// ---------------- index dtype detection + conversion ----------------
__global__ void detect_kernel(const unsigned int* __restrict__ ei) {
    int ok = 1;
    for (int i = 0; i < 256; i++) {
        if (ei[2 * i + 1] != 0u) { ok = 0; break; }
    }
    g_is64 = ok;
}

__global__ void convert_kernel(const void* __restrict__ ei, const void* __restrict__ bt) {
    const int is64 = g_is64;
    int i = blockIdx.x * blockDim.x + threadIdx.x;
    int stride = gridDim.x * blockDim.x;
    for (int k = i; k < EE; k += stride) {
        if (is64) {
            g_src[k] = (int)((const long long*)ei)[k];
            g_dst[k] = (int)((const long long*)ei)[EE + k];
        } else {
            g_src[k] = ((const int*)ei)[k];
            g_dst[k] = ((const int*)ei)[EE + k];
        }
    }
    for (int k = i; k < NN; k += stride) {
        g_batchv[k] = is64 ? (int)((const long long*)bt)[k] : ((const int*)bt)[k];
    }
}

// ---------------- node embedding ----------------
__global__ void node_embed_kernel(const float* __restrict__ x,
                                  const float* __restrict__ Wn,
                                  const float* __restrict__ bn) {
    __shared__ float sW[NDIM * HH];
    __shared__ float sb[HH];
    for (int i = threadIdx.x; i < NDIM * HH; i += blockDim.x) sW[i] = Wn[i];
    if (threadIdx.x < HH) sb[threadIdx.x] = bn[threadIdx.x];
    __syncthreads();
    int g = blockIdx.x * blockDim.x + threadIdx.x;
    int stride = gridDim.x * blockDim.x;
    const int total = NN * 32;
    for (; g < total; g += stride) {
        int n = g >> 5;
        int c = (g & 31) * 4;
        const float* xr = x + (size_t)n * NDIM;
        float4 o = make_float4(sb[c], sb[c + 1], sb[c + 2], sb[c + 3]);
#pragma unroll
        for (int k = 0; k < NDIM; k++) {
            float a = __ldg(xr + k);
            float4 w = *(const float4*)&sW[k * HH + c];
            o.x = fmaf(a, w.x, o.x); o.y = fmaf(a, w.y, o.y);
            o.z = fmaf(a, w.z, o.z); o.w = fmaf(a, w.w, o.w);
        }
        *(float4*)&g_h[(size_t)n * HH + c] = o;
    }
}

// ---------------- fused edge weights: Wec = We @ W1c, b1e = b1 + be@W1c ----
__global__ void fuse_wec_kernel(const float* __restrict__ We,
                                const float* __restrict__ be,
                                const float* __restrict__ mW1,
                                const float* __restrict__ mb1) {
    const int l = blockIdx.x;
    const float* W1c = mW1 + (size_t)l * 3 * HH * HH + 2 * HH * HH;
    const float* b1 = mb1 + l * HH;
    float* wec = g_wec + (size_t)l * EDIM * HH;
    const int t = threadIdx.x;
    for (int idx = t; idx < EDIM * HH; idx += blockDim.x) {
        int d = idx >> 7;
        int c = idx & 127;
        float s = 0.f;
        for (int j = 0; j < HH; j++)
            s = fmaf(We[d * HH + j], W1c[j * HH + c], s);
        wec[idx] = s;
    }
    if (t < HH) {
        float s = b1[t];
        for (int j = 0; j < HH; j++)
            s = fmaf(be[j], W1c[j * HH + t], s);
        g_b1e[l * HH + t] = s;
    }
}

// ---------------- Pa/Pb precompute: out = h @ W1{a|b}  (K=128, no bias) -----
__global__ __launch_bounds__(256)
void pa_pb_kernel(const float* __restrict__ W1) {
    __shared__ float sA[BK * BM];
    __shared__ float sB[BK * HH];

    const int tid = threadIdx.x;
    const int nbase = blockIdx.x * BM;
    const int tx = tid & 15;
    const int ty = tid >> 4;
    const int r_g = tid >> 1;
    const int kq = (tid & 1) * 8;
    int gnode = nbase + r_g;
    if (gnode >= NN) gnode = NN - 1;
    const float* bp = g_h + (size_t)gnode * HH;
    const float* wb = W1 + (size_t)blockIdx.y * HH * HH;
    float* outp = blockIdx.y ? g_pb : g_pa;

    float acc[8][8];
#pragma unroll
    for (int i = 0; i < 8; i++)
#pragma unroll
        for (int j = 0; j < 8; j++) acc[i][j] = 0.f;

    const int wkr = (tid * 2) >> 5;
    const int wc4 = ((tid * 2) & 31) * 4;

#pragma unroll 1
    for (int kt = 0; kt < HH; kt += BK) {
        float4 v0 = *(const float4*)(bp + kt + kq);
        float4 v1 = *(const float4*)(bp + kt + kq + 4);
        sA[(kq + 0) * BM + r_g] = v0.x;
        sA[(kq + 1) * BM + r_g] = v0.y;
        sA[(kq + 2) * BM + r_g] = v0.z;
        sA[(kq + 3) * BM + r_g] = v0.w;
        sA[(kq + 4) * BM + r_g] = v1.x;
        sA[(kq + 5) * BM + r_g] = v1.y;
        sA[(kq + 6) * BM + r_g] = v1.z;
        sA[(kq + 7) * BM + r_g] = v1.w;
        const float* wp = wb + (size_t)(kt + wkr) * HH + wc4;
        *(float4*)&sB[wkr * HH + wc4]     = *(const float4*)wp;
        *(float4*)&sB[wkr * HH + wc4 + 4] = *(const float4*)(wp + 4);
        __syncthreads();
#pragma unroll
        for (int k = 0; k < BK; k++) {
            float4 a0 = *(float4*)&sA[k * BM + ty * 4];
            float4 a1 = *(float4*)&sA[k * BM + 64 + ty * 4];
            float4 bb0 = *(float4*)&sB[k * HH + tx * 4];
            float4 bb1 = *(float4*)&sB[k * HH + 64 + tx * 4];
            float a[8] = {a0.x, a0.y, a0.z, a0.w, a1.x, a1.y, a1.z, a1.w};
            float b[8] = {bb0.x, bb0.y, bb0.z, bb0.w, bb1.x, bb1.y, bb1.z, bb1.w};
#pragma unroll
            for (int i = 0; i < 8; i++)
#pragma unroll
                for (int j = 0; j < 8; j++)
                    acc[i][j] = fmaf(a[i], b[j], acc[i][j]);
        }
        __syncthreads();
    }

#pragma unroll
    for (int i = 0; i < 8; i++) {
        int r = (i < 4) ? (ty * 4 + i) : (64 + ty * 4 + (i - 4));
        int node = nbase + r;
        if (node < NN) {
            float* op = outp + (size_t)node * HH;
            float4 v0 = make_float4(acc[i][0], acc[i][1], acc[i][2], acc[i][3]);
            float4 v1 = make_float4(acc[i][4], acc[i][5], acc[i][6], acc[i][7]);
            *(float4*)(op + tx * 4) = v0;
            *(float4*)(op + 64 + tx * 4) = v1;
        }
    }
}

// ---------------- zeroing ----------------
__global__ void zero_aggr_kernel() {
    int i = blockIdx.x * blockDim.x + threadIdx.x;
    int stride = gridDim.x * blockDim.x;
    float4 z = make_float4(0.f, 0.f, 0.f, 0.f);
    const int n4 = NN * HH / 4;
    for (int k = i; k < n4; k += stride) ((float4*)g_aggr)[k] = z;
}

__global__ void zero_pool_kernel() {
    for (int k = threadIdx.x; k < BBATCH * HH; k += blockDim.x) g_pooled[k] = 0.f;
    if (threadIdx.x < BBATCH) g_counts[threadIdx.x] = 0.f;
}

// ---------------- fused edge MLP + scatter (restructured) -------------------
// hidden = relu(Pa[dst] + Pb[src] + edge_attr@Wec + b1e); out = hidden@W2 + b2
// smem: sH[HH*BM] + sB[BK*HH] + sWec[EDIM*HH] + sDst[BM] + sSrc[BM]
__global__ __launch_bounds__(256, 2)
void edge_mlp2_kernel(const float* __restrict__ ea, int l,
                      const float* __restrict__ W2, const float* __restrict__ b2v) {
    extern __shared__ float smem[];
    float* sH = smem;                       // HH*BM
    float* sB = sH + HH * BM;               // BK*HH
    float* sWec = sB + BK * HH;             // EDIM*HH
    int* sDst = (int*)(sWec + EDIM * HH);
    int* sSrc = sDst + BM;

    const int tid = threadIdx.x;
    const int ebase = blockIdx.x * BM;
    const int tx = tid & 15;
    const int ty = tid >> 4;

    if (tid < BM) sDst[tid] = g_dst[ebase + tid];
    else          sSrc[tid - BM] = g_src[ebase + tid - BM];
    {
        const float* wsrc = g_wec + (size_t)l * EDIM * HH;
        for (int i = tid; i < EDIM * HH; i += 256) sWec[i] = wsrc[i];
    }
    __syncthreads();

    // -------- phase 1: hidden (K=16 GEMM + gathered adds) --------
    {
        const int r = tid >> 1;
        const int cb = (tid & 1) * 64;
        const float* pa = g_pa + (size_t)sDst[r] * HH + cb;
        const float* pb = g_pb + (size_t)sSrc[r] * HH + cb;
        const float* earow = ea + (size_t)(ebase + r) * EDIM;
        float eav[16];
#pragma unroll
        for (int k = 0; k < 16; k += 4) {
            float4 t4 = *(const float4*)(earow + k);
            eav[k] = t4.x; eav[k + 1] = t4.y; eav[k + 2] = t4.z; eav[k + 3] = t4.w;
        }
        const float* b1e = g_b1e + l * HH + cb;
#pragma unroll 4
        for (int c0 = 0; c0 < 64; c0 += 4) {
            float4 a = *(const float4*)(pa + c0);
            float4 b = *(const float4*)(pb + c0);
            float4 bb = *(const float4*)(b1e + c0);
            float sx = a.x + b.x + bb.x;
            float sy = a.y + b.y + bb.y;
            float sz = a.z + b.z + bb.z;
            float sw = a.w + b.w + bb.w;
#pragma unroll
            for (int k = 0; k < 16; k++) {
                float4 w = *(const float4*)&sWec[k * HH + cb + c0];
                sx = fmaf(eav[k], w.x, sx);
                sy = fmaf(eav[k], w.y, sy);
                sz = fmaf(eav[k], w.z, sz);
                sw = fmaf(eav[k], w.w, sw);
            }
            sH[(cb + c0 + 0) * BM + r] = fmaxf(sx, 0.f);
            sH[(cb + c0 + 1) * BM + r] = fmaxf(sy, 0.f);
            sH[(cb + c0 + 2) * BM + r] = fmaxf(sz, 0.f);
            sH[(cb + c0 + 3) * BM + r] = fmaxf(sw, 0.f);
        }
    }
    __syncthreads();

    // -------- phase 2: out = hidden @ W2 --------
    float acc[8][8];
#pragma unroll
    for (int i = 0; i < 8; i++)
#pragma unroll
        for (int j = 0; j < 8; j++) acc[i][j] = 0.f;

    const int wkr = (tid * 2) >> 5;
    const int wc4 = ((tid * 2) & 31) * 4;

#pragma unroll 1
    for (int kt = 0; kt < HH; kt += BK) {
        const float* wp = W2 + (size_t)(kt + wkr) * HH + wc4;
        *(float4*)&sB[wkr * HH + wc4]     = *(const float4*)wp;
        *(float4*)&sB[wkr * HH + wc4 + 4] = *(const float4*)(wp + 4);
        __syncthreads();
#pragma unroll
        for (int k = 0; k < BK; k++) {
            float4 a0 = *(float4*)&sH[(kt + k) * BM + ty * 4];
            float4 a1 = *(float4*)&sH[(kt + k) * BM + 64 + ty * 4];
            float4 bb0 = *(float4*)&sB[k * HH + tx * 4];
            float4 bb1 = *(float4*)&sB[k * HH + 64 + tx * 4];
            float a[8] = {a0.x, a0.y, a0.z, a0.w, a1.x, a1.y, a1.z, a1.w};
            float b[8] = {bb0.x, bb0.y, bb0.z, bb0.w, bb1.x, bb1.y, bb1.z, bb1.w};
#pragma unroll
            for (int i = 0; i < 8; i++)
#pragma unroll
                for (int j = 0; j < 8; j++)
                    acc[i][j] = fmaf(a[i], b[j], acc[i][j]);
        }
        __syncthreads();
    }

    // -------- scatter: aggr[dst] += out (vector reductions) --------
    float bias2[8];
#pragma unroll
    for (int j = 0; j < 8; j++) {
        int c = (j < 4) ? (tx * 4 + j) : (64 + tx * 4 + (j - 4));
        bias2[j] = b2v[c];
    }
#pragma unroll
    for (int i = 0; i < 8; i++) {
        int r = (i < 4) ? (ty * 4 + i) : (64 + ty * 4 + (i - 4));
        float* op = g_aggr + (size_t)sDst[r] * HH;
        float v0x = acc[i][0] + bias2[0];
        float v0y = acc[i][1] + bias2[1];
        float v0z = acc[i][2] + bias2[2];
        float v0w = acc[i][3] + bias2[3];
        float v1x = acc[i][4] + bias2[4];
        float v1y = acc[i][5] + bias2[5];
        float v1z = acc[i][6] + bias2[6];
        float v1w = acc[i][7] + bias2[7];
        asm volatile("red.global.add.v4.f32 [%0], {%1, %2, %3, %4};"
                     :: "l"(op + tx * 4), "f"(v0x), "f"(v0y), "f"(v0z), "f"(v0w)
                     : "memory");
        asm volatile("red.global.add.v4.f32 [%0], {%1, %2, %3, %4};"
                     :: "l"(op + 64 + tx * 4), "f"(v1x), "f"(v1y), "f"(v1z), "f"(v1w)
                     : "memory");
    }
}

// ---------------- fused node update (K=256, in-place residual) --------------
__global__ __launch_bounds__(256, 2)
void node_mlp_kernel(const float* __restrict__ W1, const float* __restrict__ b1v,
                     const float* __restrict__ W2, const float* __restrict__ b2v) {
    extern __shared__ float smem[];
    float* sA = smem;
    float* sB = sA + BK * BM;
    float* sH = sB + BK * HH;

    const int tid = threadIdx.x;
    const int nbase = blockIdx.x * BM;
    const int tx = tid & 15;
    const int ty = tid >> 4;

    const int r_g = tid >> 1;
    const int kq = (tid & 1) * 8;
    int gnode = nbase + r_g;
    if (gnode >= NN) gnode = NN - 1;
    const float* base0 = g_h + (size_t)gnode * HH;
    const float* base1 = g_aggr + (size_t)gnode * HH;

    float acc[8][8];
#pragma unroll
    for (int i = 0; i < 8; i++)
#pragma unroll
        for (int j = 0; j < 8; j++) acc[i][j] = 0.f;

    const int wkr = (tid * 2) >> 5;
    const int wc4 = ((tid * 2) & 31) * 4;

#pragma unroll 1
    for (int reg = 0; reg < 2; reg++) {
        const float* bp = (reg == 0) ? base0 : base1;
        const float* wb = W1 + (size_t)reg * HH * HH;
#pragma unroll 1
        for (int kt = 0; kt < HH; kt += BK) {
            float4 v0 = *(const float4*)(bp + kt + kq);
            float4 v1 = *(const float4*)(bp + kt + kq + 4);
            sA[(kq + 0) * BM + r_g] = v0.x;
            sA[(kq + 1) * BM + r_g] = v0.y;
            sA[(kq + 2) * BM + r_g] = v0.z;
            sA[(kq + 3) * BM + r_g] = v0.w;
            sA[(kq + 4) * BM + r_g] = v1.x;
            sA[(kq + 5) * BM + r_g] = v1.y;
            sA[(kq + 6) * BM + r_g] = v1.z;
            sA[(kq + 7) * BM + r_g] = v1.w;
            const float* wp = wb + (size_t)(kt + wkr) * HH + wc4;
            *(float4*)&sB[wkr * HH + wc4]     = *(const float4*)wp;
            *(float4*)&sB[wkr * HH + wc4 + 4] = *(const float4*)(wp + 4);
            __syncthreads();
#pragma unroll
            for (int k = 0; k < BK; k++) {
                float4 a0 = *(float4*)&sA[k * BM + ty * 4];
                float4 a1 = *(float4*)&sA[k * BM + 64 + ty * 4];
                float4 bb0 = *(float4*)&sB[k * HH + tx * 4];
                float4 bb1 = *(float4*)&sB[k * HH + 64 + tx * 4];
                float a[8] = {a0.x, a0.y, a0.z, a0.w, a1.x, a1.y, a1.z, a1.w};
                float b[8] = {bb0.x, bb0.y, bb0.z, bb0.w, bb1.x, bb1.y, bb1.z, bb1.w};
#pragma unroll
                for (int i = 0; i < 8; i++)
#pragma unroll
                    for (int j = 0; j < 8; j++)
                        acc[i][j] = fmaf(a[i], b[j], acc[i][j]);
            }
            __syncthreads();
        }
    }

#pragma unroll
    for (int j = 0; j < 8; j++) {
        int c = (j < 4) ? (tx * 4 + j) : (64 + tx * 4 + (j - 4));
        float bb = b1v[c];
#pragma unroll
        for (int i = 0; i < 8; i++) {
            int r = (i < 4) ? (ty * 4 + i) : (64 + ty * 4 + (i - 4));
            float v = acc[i][j] + bb;
            sH[c * BM + r] = (v > 0.f) ? v : 0.f;
            acc[i][j] = 0.f;
        }
    }
    __syncthreads();

#pragma unroll 1
    for (int kt = 0; kt < HH; kt += BK) {
        const float* wp = W2 + (size_t)(kt + wkr) * HH + wc4;
        *(float4*)&sB[wkr * HH + wc4]     = *(const float4*)wp;
        *(float4*)&sB[wkr * HH + wc4 + 4] = *(const float4*)(wp + 4);
        __syncthreads();
#pragma unroll
        for (int k = 0; k < BK; k++) {
            float4 a0 = *(float4*)&sH[(kt + k) * BM + ty * 4];
            float4 a1 = *(float4*)&sH[(kt + k) * BM + 64 + ty * 4];
            float4 bb0 = *(float4*)&sB[k * HH + tx * 4];
            float4 bb1 = *(float4*)&sB[k * HH + 64 + tx * 4];
            float a[8] = {a0.x, a0.y, a0.z, a0.w, a1.x, a1.y, a1.z, a1.w};
            float b[8] = {bb0.x, bb0.y, bb0.z, bb0.w, bb1.x, bb1.y, bb1.z, bb1.w};
#pragma unroll
            for (int i = 0; i < 8; i++)
#pragma unroll
                for (int j = 0; j < 8; j++)
                    acc[i][j] = fmaf(a[i], b[j], acc[i][j]);
        }
        __syncthreads();
    }

    float bias2[8];
#pragma unroll
    for (int j = 0; j < 8; j++) {
        int c = (j < 4) ? (tx * 4 + j) : (64 + tx * 4 + (j - 4));
        bias2[j] = b2v[c];
    }
#pragma unroll
    for (int i = 0; i < 8; i++) {
        int r = (i < 4) ? (ty * 4 + i) : (64 + ty * 4 + (i - 4));
        int node = nbase + r;
        if (node < NN) {
            float* op = g_h + (size_t)node * HH;
#pragma unroll
            for (int j = 0; j < 8; j++) {
                int c = (j < 4) ? (tx * 4 + j) : (64 + tx * 4 + (j - 4));
                op[c] += acc[i][j] + bias2[j];
            }
        }
    }
}

// ---------------- pooling ----------------
__global__ void pool_kernel() {
    __shared__ float sp[BBATCH * HH];
    __shared__ float sc[BBATCH];
    for (int i = threadIdx.x; i < BBATCH * HH; i += blockDim.x) sp[i] = 0.f;
    if (threadIdx.x < BBATCH) sc[threadIdx.x] = 0.f;
    __syncthreads();
    int g = blockIdx.x * blockDim.x + threadIdx.x;
    int stride = gridDim.x * blockDim.x;
    const int total = NN * HH;
    for (int idx = g; idx < total; idx += stride) {
        int n = idx >> 7;
        int j = idx & 127;
        int b = g_batchv[n];
        atomicAdd(&sp[b * HH + j], g_h[idx]);
        if (j == 0) atomicAdd(&sc[b], 1.f);
    }
    __syncthreads();
    for (int i = threadIdx.x; i < BBATCH * HH; i += blockDim.x)
        atomicAdd(&g_pooled[i], sp[i]);
    if (threadIdx.x < BBATCH) atomicAdd(&g_counts[threadIdx.x], sc[threadIdx.x]);
}

// ---------------- readout ----------------
__global__ void readout_kernel(const float* __restrict__ gf,
                               const float* __restrict__ Wg, const float* __restrict__ bg,
                               const float* __restrict__ rW1, const float* __restrict__ rb1,
                               const float* __restrict__ rW2, const float* __restrict__ rb2,
                               const float* __restrict__ rW3, const float* __restrict__ rb3,
                               float* __restrict__ out) {
    __shared__ float fin[BBATCH * 2 * HH];
    __shared__ float h1[BBATCH * HH];
    __shared__ float h2[BBATCH * 64];
    const int t = threadIdx.x;
    for (int idx = t; idx < BBATCH * 2 * HH; idx += blockDim.x) {
        int b = idx >> 8;
        int c = idx & 255;
        float v;
        if (c < HH) {
            float cnt = g_counts[b];
            if (cnt < 1.f) cnt = 1.f;
            v = g_pooled[b * HH + c] / cnt;
        } else {
            v = gf[b] * Wg[c - HH] + bg[c - HH];
        }
        fin[idx] = v;
    }
    __syncthreads();
    for (int idx = t; idx < BBATCH * HH; idx += blockDim.x) {
        int b = idx >> 7;
        int j = idx & 127;
        float s = rb1[j];
        for (int k = 0; k < 2 * HH; k++)
            s = fmaf(fin[b * 256 + k], rW1[k * HH + j], s);
        h1[idx] = (s > 0.f) ? s : 0.f;
    }
    __syncthreads();
    for (int idx = t; idx < BBATCH * 64; idx += blockDim.x) {
        int b = idx >> 6;
        int j = idx & 63;
        float s = rb2[j];
        for (int k = 0; k < HH; k++)
            s = fmaf(h1[b * HH + k], rW2[k * 64 + j], s);
        h2[idx] = (s > 0.f) ? s : 0.f;
    }
    __syncthreads();
    if (t < BBATCH) {
        float s = rb3[0];
        for (int k = 0; k < 64; k++)
            s = fmaf(h2[t * 64 + k], rW3[k], s);
        out[t] = s;
    }
}

// ---------------- host launcher ----------------
extern "C" void kernel_launch(void* const* d_in, const int* in_sizes, int n_in,
                              void* d_out, int out_size) {
    const float *x = 0, *ea = 0, *gf = 0;
    const void  *ei = 0, *bt = 0;
    const float *Wn = 0, *bn = 0, *We = 0, *be = 0, *Wg = 0, *bg = 0;
    const float *mW1 = 0, *mb1 = 0, *mW2 = 0, *mb2 = 0;
    const float *uW1 = 0, *ub1 = 0, *uW2 = 0, *ub2 = 0;
    const float *rW1 = 0, *rb1 = 0, *rW2 = 0, *rb2 = 0, *rW3 = 0, *rb3 = 0;
    int c128 = 0, c384 = 0, c49 = 0, c64 = 0;
    for (int i = 0; i < n_in; i++) {
        const void* p = d_in[i];
        switch (in_sizes[i]) {
            case 1600000: x = (const float*)p; break;
            case 6400000: ea = (const float*)p; break;
            case 8:       gf = (const float*)p; break;
            case 800000:  ei = p; break;
            case 50000:   bt = p; break;
            case 4096:    Wn = (const float*)p; break;
            case 2048:    We = (const float*)p; break;
            case 147456:  mW1 = (const float*)p; break;
            case 98304:   uW1 = (const float*)p; break;
            case 32768:   rW1 = (const float*)p; break;
            case 8192:    rW2 = (const float*)p; break;
            case 1:       rb3 = (const float*)p; break;
            case 128:
                if (c128 == 0) bn = (const float*)p;
                else if (c128 == 1) be = (const float*)p;
                else if (c128 == 2) Wg = (const float*)p;
                else if (c128 == 3) bg = (const float*)p;
                else rb1 = (const float*)p;
                c128++;
                break;
            case 384:
                if (c384 == 0) mb1 = (const float*)p;
                else if (c384 == 1) mb2 = (const float*)p;
                else if (c384 == 2) ub1 = (const float*)p;
                else ub2 = (const float*)p;
                c384++;
                break;
            case 49152:
                if (c49 == 0) mW2 = (const float*)p;
                else uW2 = (const float*)p;
                c49++;
                break;
            case 64:
                if (c64 == 0) rb2 = (const float*)p;
                else rW3 = (const float*)p;
                c64++;
                break;
            default: break;
        }
    }
    float* out = (float*)d_out;
    (void)out_size;

    const int SMEM_EDGE = (HH * BM + BK * HH + EDIM * HH) * 4 + 2 * BM * 4;
    const int SMEM_NODE = (BK * BM + BK * HH + HH * BM) * 4;
    cudaFuncSetAttribute(edge_mlp2_kernel, cudaFuncAttributeMaxDynamicSharedMemorySize, SMEM_EDGE);
    cudaFuncSetAttribute(node_mlp_kernel, cudaFuncAttributeMaxDynamicSharedMemorySize, SMEM_NODE);

    detect_kernel<<<1, 1>>>((const unsigned int*)ei);
    convert_kernel<<<1024, 256>>>(ei, bt);
    node_embed_kernel<<<3200, 256>>>(x, Wn, bn);
    fuse_wec_kernel<<<LL, 256>>>(We, be, mW1, mb1);

    const int NB_NODE = (NN + BM - 1) / BM;  // 391
    for (int l = 0; l < LL; l++) {
        pa_pb_kernel<<<dim3(NB_NODE, 2), 256>>>(mW1 + (size_t)l * 3 * HH * HH);
        zero_aggr_kernel<<<1600, 256>>>();
        edge_mlp2_kernel<<<EE / BM, 256, SMEM_EDGE>>>(
            ea, l, mW2 + (size_t)l * HH * HH, mb2 + l * HH);
        node_mlp_kernel<<<NB_NODE, 256, SMEM_NODE>>>(
            uW1 + (size_t)l * 2 * HH * HH, ub1 + l * HH,
            uW2 + (size_t)l * HH * HH, ub2 + l * HH);
    }

    zero_pool_kernel<<<1, 256>>>();
    pool_kernel<<<1024, 256>>>();
    readout_kernel<<<1, 256>>>(gf, Wg, bg, rW1, rb1, rW2, rb2, rW3, rb3, out);
}